// round 16
// baseline (speedup 1.0000x reference)
#include <cuda_runtime.h>
#include <cuda_fp16.h>
#include <mma.h>
#include <math.h>

using namespace nvcuda;

#define N_NODES 50000
#define N_PAD   50048   // multiple of 128 for wmma tiles
#define N_EDGES 800000
#define FIN0 16
#define DM 96
#define NG 64
#define NBLK_N 196   // ceil(50000/256)

// ---------------- device scratch (no allocations allowed) ----------------
__device__ __align__(16) __half g_h[N_PAD * DM];      // h' = dis*(X@W), fp16, 192B rows
__device__ __align__(16) __half g_x16[N_NODES * DM];  // x' = dis*x, fp16, SAME 192B stride (16 used)
__device__ __align__(16) __half g_aggx16[N_PAD * FIN0]; // layer-1 aggregate, fp16
__device__ __align__(16) __half g_agg16[N_PAD * DM];  // conv output (lrelu), fp16
__device__ float g_dis[N_PAD];           // deg^{-1/2}; pad rows = 0
__device__ int   g_deg[N_NODES];         // includes self-loop
__device__ int   g_rowstart[N_NODES + 1];
__device__ int   g_cursor[N_NODES];
__device__ int   g_bsum[NBLK_N];
__device__ int   g_boff[NBLK_N];
__device__ int   g_csr_src24[N_EDGES];   // src * 24 (float2-unit offset of 192B row)
__device__ int   g_gcnt[NG];
__device__ int   g_goff[NG + 1];
__device__ int   g_is64;

__device__ __forceinline__ float lrelu(float v) { return v > 0.0f ? v : 0.01f * v; }

__device__ __forceinline__ long long read_idx(const void* p, long long i) {
    if (g_is64) return ((const long long*)p)[i];
    return (long long)((const int*)p)[i];
}

// ---------------- init: dtype detect + deg/gcnt init ------------------------
__global__ void init_k(const int* __restrict__ ei32) {
    int i = blockIdx.x * blockDim.x + threadIdx.x;
    if (blockIdx.x == 0) {
        __shared__ int nz;
        if (threadIdx.x == 0) nz = 0;
        __syncthreads();
        for (int k = threadIdx.x; k < 4096; k += blockDim.x)
            if (ei32[2 * k + 1] != 0) atomicAdd(&nz, 1);
        __syncthreads();
        if (threadIdx.x == 0) g_is64 = (nz == 0) ? 1 : 0;
    }
    if (i < N_NODES) g_deg[i] = 1;  // self-loop
    else if (i < N_PAD) g_dis[i] = 0.0f;  // zero pad norm
    if (i < NG) g_gcnt[i] = 0;
}

// ---------------- counts ----------------------------------------------------
__global__ void count_k(const void* __restrict__ ei, const void* __restrict__ batch) {
    int e = blockIdx.x * blockDim.x + threadIdx.x;
    if (e < N_EDGES) atomicAdd(&g_deg[(int)read_idx(ei, (long long)N_EDGES + e)], 1);
    if (e < N_NODES) atomicAdd(&g_gcnt[(int)read_idx(batch, e)], 1);
}

// ---------------- scan level 1 (+ rsqrt + x scale into 192B-stride rows) ----
__global__ void scanpart_dis_k(const float* __restrict__ x) {
    __shared__ int sm[256];
    int i = blockIdx.x * 256 + threadIdx.x;
    int d = (i < N_NODES) ? g_deg[i] : 1;
    if (i < N_NODES) {
        float dn = rsqrtf((float)d);
        g_dis[i] = dn;
        const float* xr = x + (size_t)i * FIN0;
        __half2* o = (__half2*)(g_x16 + (size_t)i * DM);  // 192B stride
#pragma unroll
        for (int f = 0; f < FIN0 / 2; f++)
            o[f] = __floats2half2_rn(xr[2 * f] * dn, xr[2 * f + 1] * dn);
    }
    sm[threadIdx.x] = (i < N_NODES) ? d - 1 : 0;
    __syncthreads();
    for (int off = 128; off > 0; off >>= 1) {
        if (threadIdx.x < off) sm[threadIdx.x] += sm[threadIdx.x + off];
        __syncthreads();
    }
    if (threadIdx.x == 0) g_bsum[blockIdx.x] = sm[0];
}

// ---------------- scan top level + graph offsets ----------------------------
__global__ void scantop_goff_k() {
    __shared__ int s[256];
    __shared__ int sg[NG];
    int t = threadIdx.x;
    int own = (t < NBLK_N) ? g_bsum[t] : 0;
    s[t] = own;
    if (t < NG) sg[t] = g_gcnt[t];
    __syncthreads();
    for (int off = 1; off < 256; off <<= 1) {
        int v = (t >= off) ? s[t - off] : 0;
        int vg = (t < NG && t >= off) ? sg[t - off] : 0;
        __syncthreads();
        s[t] += v;
        if (t < NG) sg[t] += vg;
        __syncthreads();
    }
    if (t < NBLK_N) g_boff[t] = s[t] - own;
    if (t < NG) g_goff[t + 1] = sg[t];
    if (t == 0) { g_rowstart[N_NODES] = N_EDGES; g_goff[0] = 0; }
}

__global__ void scan_down_k() {
    __shared__ int sm[256];
    int t = threadIdx.x;
    int i = blockIdx.x * 256 + t;
    int v = (i < N_NODES) ? g_deg[i] - 1 : 0;
    sm[t] = v;
    __syncthreads();
    for (int off = 1; off < 256; off <<= 1) {
        int u = (t >= off) ? sm[t - off] : 0;
        __syncthreads();
        sm[t] += u;
        __syncthreads();
    }
    if (i < N_NODES) {
        int rs = g_boff[blockIdx.x] + sm[t] - v;
        g_rowstart[i] = rs;
        g_cursor[i] = rs;
    }
}

__global__ void bucket_k(const void* __restrict__ ei) {
    int e = blockIdx.x * blockDim.x + threadIdx.x;
    if (e >= N_EDGES) return;
    int s = (int)read_idx(ei, e);
    int d = (int)read_idx(ei, (long long)N_EDGES + e);
    int pos = atomicAdd(&g_cursor[d], 1);
    g_csr_src24[pos] = s * 24;   // pre-scaled float2-unit row offset
}

// ---------------- layer-1 gather in 16-dim input space ----------------------
// aggx16[d] = half(dis[d] * (x'[d] + sum x'[src])); 8 lanes per node.
// x16 rows share the 192B stride: half2 index = off24*2 + sub.
__global__ void gather16_k() {
    int gtid = blockIdx.x * blockDim.x + threadIdx.x;
    int node = gtid >> 3;
    if (node >= N_NODES) return;
    int sub = gtid & 7;
    const __half2* x2 = (const __half2*)g_x16;
    int beg = g_rowstart[node], end = g_rowstart[node + 1];
    float dn = g_dis[node];
    float2 acc = __half22float2(__ldg(&x2[(size_t)node * 48 + sub]));  // self
    int j = beg;
    for (; j + 3 < end; j += 4) {
        int o0 = __ldg(&g_csr_src24[j]);
        int o1 = __ldg(&g_csr_src24[j + 1]);
        int o2 = __ldg(&g_csr_src24[j + 2]);
        int o3 = __ldg(&g_csr_src24[j + 3]);
        float2 v0 = __half22float2(__ldg(&x2[(size_t)(o0 * 2 + sub)]));
        float2 v1 = __half22float2(__ldg(&x2[(size_t)(o1 * 2 + sub)]));
        float2 v2 = __half22float2(__ldg(&x2[(size_t)(o2 * 2 + sub)]));
        float2 v3 = __half22float2(__ldg(&x2[(size_t)(o3 * 2 + sub)]));
        acc.x += (v0.x + v1.x) + (v2.x + v3.x);
        acc.y += (v0.y + v1.y) + (v2.y + v3.y);
    }
    for (; j < end; j++) {
        int o = __ldg(&g_csr_src24[j]);
        float2 v = __half22float2(__ldg(&x2[(size_t)(o * 2 + sub)]));
        acc.x += v.x; acc.y += v.y;
    }
    ((__half2*)g_aggx16)[(size_t)node * 8 + sub] = __floats2half2_rn(acc.x * dn, acc.y * dn);
}

// ---------------- wmma GEMM: out = A[fp16] @ W, 128x96 tile -----------------
// EPI 0: g_h = half(dis * (A@W))     (for gather)
// EPI 1: g_agg16 = half(lrelu(A@W + b))  (layer-1 output)
template <int KDIM, int EPI>
__global__ void gemm_wmma_k(const __half* __restrict__ A, const float* __restrict__ Wf,
                            const float* __restrict__ b) {
    __shared__ __half Bs[KDIM * DM];
    __shared__ float bias_s[DM];
    __shared__ float stage[8][16 * 48];   // half-width staging per warp (24KB)
    int tid = threadIdx.x;
    for (int i = tid; i < KDIM * DM; i += 256) Bs[i] = __float2half(Wf[i]);
    if (EPI == 1) { if (tid < DM) bias_s[tid] = b[tid]; }
    __syncthreads();

    int warp = tid >> 5;
    int lane = tid & 31;
    int row0 = blockIdx.x * 128 + warp * 16;

    wmma::fragment<wmma::accumulator, 16, 16, 16, float> c[6];
#pragma unroll
    for (int j = 0; j < 6; j++) wmma::fill_fragment(c[j], 0.0f);
#pragma unroll
    for (int k = 0; k < KDIM / 16; k++) {
        wmma::fragment<wmma::matrix_a, 16, 16, 16, __half, wmma::row_major> a;
        wmma::load_matrix_sync(a, A + (size_t)row0 * KDIM + k * 16, KDIM);
#pragma unroll
        for (int j = 0; j < 6; j++) {
            wmma::fragment<wmma::matrix_b, 16, 16, 16, __half, wmma::row_major> bf;
            wmma::load_matrix_sync(bf, Bs + k * 16 * DM + j * 16, DM);
            wmma::mma_sync(c[j], a, bf, c[j]);
        }
    }

#pragma unroll
    for (int half_id = 0; half_id < 2; half_id++) {
        int c0 = half_id * 48;
#pragma unroll
        for (int j = 0; j < 3; j++)
            wmma::store_matrix_sync(&stage[warp][j * 16], c[half_id * 3 + j], 48,
                                    wmma::mem_row_major);
        __syncwarp();
        // 16 rows x 48 cols = 16 x 24 half2
        for (int i = lane; i < 16 * 24; i += 32) {
            int r = i / 24, cp = i % 24;
            float v0 = stage[warp][r * 48 + 2 * cp];
            float v1 = stage[warp][r * 48 + 2 * cp + 1];
            int grow = row0 + r;
            if (EPI == 0) {
                float dn = g_dis[grow];
                ((__half2*)(g_h + (size_t)grow * DM + c0))[cp] =
                    __floats2half2_rn(v0 * dn, v1 * dn);
            } else {
                ((__half2*)(g_agg16 + (size_t)grow * DM + c0))[cp] =
                    __floats2half2_rn(lrelu(v0 + bias_s[c0 + 2 * cp]),
                                      lrelu(v1 + bias_s[c0 + 2 * cp + 1]));
            }
        }
        __syncwarp();
    }
}

// ---------------- gather: agg16 = lrelu(b + dis[d]*(h'[d] + sum h'[src])) ---
// fp16 rows (192B). 24 active lanes, float2 per lane, pre-scaled offsets.
__global__ void gather_k(const float* __restrict__ b) {
    int w = (blockIdx.x * blockDim.x + threadIdx.x) >> 5;
    if (w >= N_NODES) return;
    int lane = threadIdx.x & 31;
    bool act = lane < 24;
    int beg = g_rowstart[w], end = g_rowstart[w + 1];
    float dn = g_dis[w];
    const float2* h2 = (const float2*)g_h;  // 24 float2 per row
    float4 acc = make_float4(0.f, 0.f, 0.f, 0.f);

#define ACC_ROW(raw) do {                                              \
        __half2 p0 = *reinterpret_cast<const __half2*>(&(raw).x);      \
        __half2 p1 = *reinterpret_cast<const __half2*>(&(raw).y);      \
        float2 f0 = __half22float2(p0), f1 = __half22float2(p1);       \
        acc.x += f0.x; acc.y += f0.y; acc.z += f1.x; acc.w += f1.y;    \
    } while (0)

    if (act) { float2 rw = __ldg(&h2[(size_t)w * 24 + lane]); ACC_ROW(rw); }
    int j = beg;
    for (; j + 7 < end; j += 8) {
        int o[8];
#pragma unroll
        for (int u = 0; u < 8; u++) o[u] = __ldg(&g_csr_src24[j + u]);
        if (act) {
            float2 r[8];
#pragma unroll
            for (int u = 0; u < 8; u++) r[u] = __ldg(&h2[(size_t)(o[u] + lane)]);
#pragma unroll
            for (int u = 0; u < 8; u++) ACC_ROW(r[u]);
        }
    }
    for (; j + 1 < end; j += 2) {
        int o0 = __ldg(&g_csr_src24[j]);
        int o1 = __ldg(&g_csr_src24[j + 1]);
        if (act) {
            float2 r0 = __ldg(&h2[(size_t)(o0 + lane)]);
            float2 r1 = __ldg(&h2[(size_t)(o1 + lane)]);
            ACC_ROW(r0); ACC_ROW(r1);
        }
    }
    if (j < end) {
        int o = __ldg(&g_csr_src24[j]);
        if (act) { float2 r = __ldg(&h2[(size_t)(o + lane)]); ACC_ROW(r); }
    }
#undef ACC_ROW

    if (act) {
        float4 bb = *(const float4*)(b + lane * 4);
        __half2 o0 = __floats2half2_rn(lrelu(fmaf(dn, acc.x, bb.x)),
                                       lrelu(fmaf(dn, acc.y, bb.y)));
        __half2 o1 = __floats2half2_rn(lrelu(fmaf(dn, acc.z, bb.z)),
                                       lrelu(fmaf(dn, acc.w, bb.w)));
        float2 pk;
        *reinterpret_cast<__half2*>(&pk.x) = o0;
        *reinterpret_cast<__half2*>(&pk.y) = o1;
        ((float2*)g_agg16)[(size_t)w * 24 + lane] = pk;
    }
}

// ---------------- fused tail: pooling + MLP1 + MLP2 (fp16 agg) --------------
__global__ void tail_k(const float* __restrict__ Wo1, const float* __restrict__ bo1,
                       const float* __restrict__ Wo2, const float* __restrict__ bo2,
                       float* __restrict__ out) {
    int g = blockIdx.x;
    int beg = g_goff[g], end = g_goff[g + 1];
    int t = threadIdx.x;                 // 288 threads = 3 x 96
    int f = t % DM, rr = t / DM;
    __shared__ float smx[288], ssm[288];
    __shared__ float pooled[2 * DM];
    __shared__ float hidden[DM];

    float mx = -INFINITY, sm = 0.0f;
    for (int n = beg + rr; n < end; n += 3) {
        float v = __half2float(g_agg16[(size_t)n * DM + f]);
        mx = fmaxf(mx, v);
        sm += v;
    }
    smx[t] = mx;
    ssm[t] = sm;
    __syncthreads();
    if (rr == 0) {
        mx = fmaxf(fmaxf(smx[f], smx[f + DM]), smx[f + 2 * DM]);
        sm = ssm[f] + ssm[f + DM] + ssm[f + 2 * DM];
        pooled[f] = mx;
        pooled[DM + f] = sm / fmaxf((float)(end - beg), 1.0f);
    }
    __syncthreads();
    if (t < DM) {
        float acc = bo1[t];
#pragma unroll 8
        for (int k = 0; k < 2 * DM; k++) acc = fmaf(pooled[k], Wo1[k * DM + t], acc);
        hidden[t] = lrelu(acc);
    }
    __syncthreads();
    if (t < 32) {
        float a = 0.0f;
#pragma unroll
        for (int k = t; k < DM; k += 32) a = fmaf(hidden[k], Wo2[k], a);
#pragma unroll
        for (int o = 16; o; o >>= 1) a += __shfl_down_sync(0xffffffff, a, o);
        if (t == 0) out[g] = a + bo2[0];
    }
}

// ---------------- host orchestration ---------------------------------------
extern "C" void kernel_launch(void* const* d_in, const int* in_sizes, int n_in,
                              void* d_out, int out_size) {
    const float* x      = (const float*)d_in[0];
    const void*  ei     = d_in[1];
    const void*  batch  = d_in[2];
    const float* W_init = (const float*)d_in[3];
    const float* b_init = (const float*)d_in[4];
    const float* Wl[4]  = {(const float*)d_in[5], (const float*)d_in[7],
                           (const float*)d_in[9], (const float*)d_in[11]};
    const float* bl[4]  = {(const float*)d_in[6], (const float*)d_in[8],
                           (const float*)d_in[10], (const float*)d_in[12]};
    const float* Wo1    = (const float*)d_in[13];
    const float* bo1    = (const float*)d_in[14];
    const float* Wo2    = (const float*)d_in[15];
    const float* bo2    = (const float*)d_in[16];
    float* out = (float*)d_out;

    __half* p_aggx16 = nullptr;
    __half* p_agg16 = nullptr;
    cudaGetSymbolAddress((void**)&p_aggx16, g_aggx16);
    cudaGetSymbolAddress((void**)&p_agg16, g_agg16);

    const int T = 256;
    const int gridE   = (N_EDGES + T - 1) / T;
    const int gridG   = (N_NODES * 32 + T - 1) / T;   // warp per node
    const int gridG16 = (N_NODES * 8 + T - 1) / T;    // 8 lanes per node
    const int gridMM  = N_PAD / 128;                  // 391

    init_k<<<NBLK_N, T>>>((const int*)ei);
    count_k<<<gridE, T>>>(ei, batch);
    scanpart_dis_k<<<NBLK_N, T>>>(x);
    scantop_goff_k<<<1, T>>>();
    scan_down_k<<<NBLK_N, T>>>();
    bucket_k<<<gridE, T>>>(ei);

    // layer 1: aggregate in 16-dim input space, then wmma GEMM + lrelu(+b)
    gather16_k<<<gridG16, T>>>();
    gemm_wmma_k<FIN0, 1><<<gridMM, 256>>>(p_aggx16, W_init, b_init);

    // layers 2..5 (K=96)
    for (int l = 0; l < 4; l++) {
        gemm_wmma_k<DM, 0><<<gridMM, 256>>>(p_agg16, Wl[l], nullptr);
        gather_k<<<gridG, T>>>(bl[l]);
    }

    // fused pooling + MLP head
    tail_k<<<NG, 288>>>(Wo1, bo1, Wo2, bo2, out);
}

// round 17
// speedup vs baseline: 1.4207x; 1.4207x over previous
#include <cuda_runtime.h>
#include <cuda_fp16.h>
#include <mma.h>
#include <math.h>

using namespace nvcuda;

#define N_NODES 50000
#define N_PAD   50048   // multiple of 128 for wmma tiles
#define N_EDGES 800000
#define FIN0 16
#define DM 96
#define NG 64
#define NBLK_N 196   // ceil(50000/256)

// ---------------- device scratch (no allocations allowed) ----------------
__device__ __align__(16) __half g_h[N_PAD * DM];      // h' = dis*(X@W), fp16
__device__ __align__(16) __half g_x16[N_NODES * FIN0];// x' = dis*x, fp16
__device__ __align__(16) __half g_aggx16[N_PAD * FIN0]; // layer-1 aggregate, fp16
__device__ __align__(16) __half g_agg16[N_PAD * DM];  // conv output (lrelu), fp16
__device__ float g_dis[N_PAD];           // deg^{-1/2}; pad rows = 0
__device__ int   g_deg[N_NODES];         // includes self-loop
__device__ int   g_rowstart[N_NODES + 1];
__device__ int   g_cursor[N_NODES];
__device__ int   g_bsum[NBLK_N];
__device__ int   g_boff[NBLK_N];
__device__ int   g_csr_src[N_EDGES];
__device__ int   g_gcnt[NG];
__device__ int   g_goff[NG + 1];
__device__ int   g_is64;

__device__ __forceinline__ float lrelu(float v) { return v > 0.0f ? v : 0.01f * v; }

__device__ __forceinline__ long long read_idx(const void* p, long long i) {
    if (g_is64) return ((const long long*)p)[i];
    return (long long)((const int*)p)[i];
}

// packed accumulate: acc(f32x2) += cvt_f32x2(h2)  — identical fp32 math,
// but 2 F2F + 1 ADD.F32x2 instead of 2 F2F + 2 FADD per half2.
__device__ __forceinline__ void acc_h2_f32x2(unsigned long long& acc, unsigned int h2w) {
    asm("{\n\t"
        ".reg .b16 lo, hi;\n\t"
        ".reg .f32 flo, fhi;\n\t"
        ".reg .b64 v;\n\t"
        "mov.b32 {lo, hi}, %1;\n\t"
        "cvt.f32.f16 flo, lo;\n\t"
        "cvt.f32.f16 fhi, hi;\n\t"
        "mov.b64 v, {flo, fhi};\n\t"
        "add.rn.f32x2 %0, %0, v;\n\t"
        "}" : "+l"(acc) : "r"(h2w));
}

__device__ __forceinline__ float2 unpack_f32x2(unsigned long long v) {
    float2 r;
    asm("mov.b64 {%0, %1}, %2;" : "=f"(r.x), "=f"(r.y) : "l"(v));
    return r;
}

// ---------------- init: dtype detect + deg/gcnt init ------------------------
__global__ void init_k(const int* __restrict__ ei32) {
    int i = blockIdx.x * blockDim.x + threadIdx.x;
    if (blockIdx.x == 0) {
        __shared__ int nz;
        if (threadIdx.x == 0) nz = 0;
        __syncthreads();
        for (int k = threadIdx.x; k < 4096; k += blockDim.x)
            if (ei32[2 * k + 1] != 0) atomicAdd(&nz, 1);
        __syncthreads();
        if (threadIdx.x == 0) g_is64 = (nz == 0) ? 1 : 0;
    }
    if (i < N_NODES) g_deg[i] = 1;  // self-loop
    else if (i < N_PAD) g_dis[i] = 0.0f;  // zero pad norm -> zero pad h rows
    if (i < NG) g_gcnt[i] = 0;
}

// ---------------- counts ----------------------------------------------------
__global__ void count_k(const void* __restrict__ ei, const void* __restrict__ batch) {
    int e = blockIdx.x * blockDim.x + threadIdx.x;
    if (e < N_EDGES) atomicAdd(&g_deg[(int)read_idx(ei, (long long)N_EDGES + e)], 1);
    if (e < N_NODES) atomicAdd(&g_gcnt[(int)read_idx(batch, e)], 1);
}

// ---------------- scan level 1 (+ rsqrt + x scale) ---------------------------
__global__ void scanpart_dis_k(const float* __restrict__ x) {
    __shared__ int sm[256];
    int i = blockIdx.x * 256 + threadIdx.x;
    int d = (i < N_NODES) ? g_deg[i] : 1;
    if (i < N_NODES) {
        float dn = rsqrtf((float)d);
        g_dis[i] = dn;
        const float* xr = x + (size_t)i * FIN0;
        __half2* o = (__half2*)(g_x16 + (size_t)i * FIN0);
#pragma unroll
        for (int f = 0; f < FIN0 / 2; f++)
            o[f] = __floats2half2_rn(xr[2 * f] * dn, xr[2 * f + 1] * dn);
    }
    sm[threadIdx.x] = (i < N_NODES) ? d - 1 : 0;
    __syncthreads();
    for (int off = 128; off > 0; off >>= 1) {
        if (threadIdx.x < off) sm[threadIdx.x] += sm[threadIdx.x + off];
        __syncthreads();
    }
    if (threadIdx.x == 0) g_bsum[blockIdx.x] = sm[0];
}

// ---------------- scan top level + graph offsets ----------------------------
__global__ void scantop_goff_k() {
    __shared__ int s[256];
    __shared__ int sg[NG];
    int t = threadIdx.x;
    int own = (t < NBLK_N) ? g_bsum[t] : 0;
    s[t] = own;
    if (t < NG) sg[t] = g_gcnt[t];
    __syncthreads();
    for (int off = 1; off < 256; off <<= 1) {
        int v = (t >= off) ? s[t - off] : 0;
        int vg = (t < NG && t >= off) ? sg[t - off] : 0;
        __syncthreads();
        s[t] += v;
        if (t < NG) sg[t] += vg;
        __syncthreads();
    }
    if (t < NBLK_N) g_boff[t] = s[t] - own;
    if (t < NG) g_goff[t + 1] = sg[t];
    if (t == 0) { g_rowstart[N_NODES] = N_EDGES; g_goff[0] = 0; }
}

__global__ void scan_down_k() {
    __shared__ int sm[256];
    int t = threadIdx.x;
    int i = blockIdx.x * 256 + t;
    int v = (i < N_NODES) ? g_deg[i] - 1 : 0;
    sm[t] = v;
    __syncthreads();
    for (int off = 1; off < 256; off <<= 1) {
        int u = (t >= off) ? sm[t - off] : 0;
        __syncthreads();
        sm[t] += u;
        __syncthreads();
    }
    if (i < N_NODES) {
        int rs = g_boff[blockIdx.x] + sm[t] - v;
        g_rowstart[i] = rs;
        g_cursor[i] = rs;
    }
}

__global__ void bucket_k(const void* __restrict__ ei) {
    int e = blockIdx.x * blockDim.x + threadIdx.x;
    if (e >= N_EDGES) return;
    int s = (int)read_idx(ei, e);
    int d = (int)read_idx(ei, (long long)N_EDGES + e);
    int pos = atomicAdd(&g_cursor[d], 1);
    g_csr_src[pos] = s;
}

// ---------------- layer-1 gather in 16-dim input space ----------------------
// aggx16[d] = half(dis[d] * (x'[d] + sum x'[src])); 8 lanes per node.
__global__ void gather16_k() {
    int gtid = blockIdx.x * blockDim.x + threadIdx.x;
    int node = gtid >> 3;
    if (node >= N_NODES) return;
    int sub = gtid & 7;
    const unsigned int* x2 = (const unsigned int*)g_x16;  // 8 half2-words per row
    int beg = g_rowstart[node], end = g_rowstart[node + 1];
    float dn = g_dis[node];
    unsigned long long acc = 0ULL;
    acc_h2_f32x2(acc, __ldg(&x2[(size_t)node * 8 + sub]));  // self
    int j = beg;
    for (; j + 3 < end; j += 4) {
        int s0 = __ldg(&g_csr_src[j]);
        int s1 = __ldg(&g_csr_src[j + 1]);
        int s2 = __ldg(&g_csr_src[j + 2]);
        int s3 = __ldg(&g_csr_src[j + 3]);
        unsigned int v0 = __ldg(&x2[(size_t)s0 * 8 + sub]);
        unsigned int v1 = __ldg(&x2[(size_t)s1 * 8 + sub]);
        unsigned int v2 = __ldg(&x2[(size_t)s2 * 8 + sub]);
        unsigned int v3 = __ldg(&x2[(size_t)s3 * 8 + sub]);
        acc_h2_f32x2(acc, v0);
        acc_h2_f32x2(acc, v1);
        acc_h2_f32x2(acc, v2);
        acc_h2_f32x2(acc, v3);
    }
    for (; j < end; j++) {
        int s = __ldg(&g_csr_src[j]);
        acc_h2_f32x2(acc, __ldg(&x2[(size_t)s * 8 + sub]));
    }
    float2 a = unpack_f32x2(acc);
    ((__half2*)g_aggx16)[(size_t)node * 8 + sub] = __floats2half2_rn(a.x * dn, a.y * dn);
}

// ---------------- wmma GEMM: out = A[fp16] @ W, 128x96 tile -----------------
// EPI 0: g_h = half(dis * (A@W))     (for gather)
// EPI 1: g_agg16 = half(lrelu(A@W + b))  (layer-1 output)
template <int KDIM, int EPI>
__global__ void gemm_wmma_k(const __half* __restrict__ A, const float* __restrict__ Wf,
                            const float* __restrict__ b) {
    __shared__ __half Bs[KDIM * DM];
    __shared__ float bias_s[DM];
    __shared__ float stage[8][16 * 48];   // half-width staging per warp (24KB)
    int tid = threadIdx.x;
    for (int i = tid; i < KDIM * DM; i += 256) Bs[i] = __float2half(Wf[i]);
    if (EPI == 1) { if (tid < DM) bias_s[tid] = b[tid]; }
    __syncthreads();

    int warp = tid >> 5;
    int lane = tid & 31;
    int row0 = blockIdx.x * 128 + warp * 16;

    wmma::fragment<wmma::accumulator, 16, 16, 16, float> c[6];
#pragma unroll
    for (int j = 0; j < 6; j++) wmma::fill_fragment(c[j], 0.0f);
#pragma unroll
    for (int k = 0; k < KDIM / 16; k++) {
        wmma::fragment<wmma::matrix_a, 16, 16, 16, __half, wmma::row_major> a;
        wmma::load_matrix_sync(a, A + (size_t)row0 * KDIM + k * 16, KDIM);
#pragma unroll
        for (int j = 0; j < 6; j++) {
            wmma::fragment<wmma::matrix_b, 16, 16, 16, __half, wmma::row_major> bf;
            wmma::load_matrix_sync(bf, Bs + k * 16 * DM + j * 16, DM);
            wmma::mma_sync(c[j], a, bf, c[j]);
        }
    }

#pragma unroll
    for (int half_id = 0; half_id < 2; half_id++) {
        int c0 = half_id * 48;
#pragma unroll
        for (int j = 0; j < 3; j++)
            wmma::store_matrix_sync(&stage[warp][j * 16], c[half_id * 3 + j], 48,
                                    wmma::mem_row_major);
        __syncwarp();
        // 16 rows x 48 cols = 16 x 24 half2
        for (int i = lane; i < 16 * 24; i += 32) {
            int r = i / 24, cp = i % 24;
            float v0 = stage[warp][r * 48 + 2 * cp];
            float v1 = stage[warp][r * 48 + 2 * cp + 1];
            int grow = row0 + r;
            if (EPI == 0) {
                float dn = g_dis[grow];
                ((__half2*)(g_h + (size_t)grow * DM + c0))[cp] =
                    __floats2half2_rn(v0 * dn, v1 * dn);
            } else {
                ((__half2*)(g_agg16 + (size_t)grow * DM + c0))[cp] =
                    __floats2half2_rn(lrelu(v0 + bias_s[c0 + 2 * cp]),
                                      lrelu(v1 + bias_s[c0 + 2 * cp + 1]));
            }
        }
        __syncwarp();
    }
}

// ---------------- gather: agg16 = lrelu(b + dis[d]*(h'[d] + sum h'[src])) ---
// fp16 rows (192B). 24 active lanes, float2 (4 features) per lane, unroll 8,
// packed f32x2 accumulation (identical fp32 math, fewer issue slots).
__global__ void gather_k(const float* __restrict__ b) {
    int w = (blockIdx.x * blockDim.x + threadIdx.x) >> 5;
    if (w >= N_NODES) return;
    int lane = threadIdx.x & 31;
    bool act = lane < 24;
    int beg = g_rowstart[w], end = g_rowstart[w + 1];
    float dn = g_dis[w];
    const float2* h2 = (const float2*)g_h;  // 24 float2 per row
    unsigned long long acc01 = 0ULL, acc23 = 0ULL;

#define ACC_ROW(raw) do {                                              \
        acc_h2_f32x2(acc01, __float_as_uint((raw).x));                 \
        acc_h2_f32x2(acc23, __float_as_uint((raw).y));                 \
    } while (0)

    if (act) { float2 rw = __ldg(&h2[(size_t)w * 24 + lane]); ACC_ROW(rw); }
    int j = beg;
    for (; j + 7 < end; j += 8) {
        int s[8];
#pragma unroll
        for (int u = 0; u < 8; u++) s[u] = __ldg(&g_csr_src[j + u]);
        if (act) {
            float2 r[8];
#pragma unroll
            for (int u = 0; u < 8; u++) r[u] = __ldg(&h2[(size_t)s[u] * 24 + lane]);
#pragma unroll
            for (int u = 0; u < 8; u++) ACC_ROW(r[u]);
        }
    }
    for (; j + 1 < end; j += 2) {
        int s0 = __ldg(&g_csr_src[j]);
        int s1 = __ldg(&g_csr_src[j + 1]);
        if (act) {
            float2 r0 = __ldg(&h2[(size_t)s0 * 24 + lane]);
            float2 r1 = __ldg(&h2[(size_t)s1 * 24 + lane]);
            ACC_ROW(r0); ACC_ROW(r1);
        }
    }
    if (j < end) {
        int s = __ldg(&g_csr_src[j]);
        if (act) { float2 r = __ldg(&h2[(size_t)s * 24 + lane]); ACC_ROW(r); }
    }
#undef ACC_ROW

    if (act) {
        float2 a01 = unpack_f32x2(acc01);
        float2 a23 = unpack_f32x2(acc23);
        float4 bb = *(const float4*)(b + lane * 4);
        __half2 o0 = __floats2half2_rn(lrelu(fmaf(dn, a01.x, bb.x)),
                                       lrelu(fmaf(dn, a01.y, bb.y)));
        __half2 o1 = __floats2half2_rn(lrelu(fmaf(dn, a23.x, bb.z)),
                                       lrelu(fmaf(dn, a23.y, bb.w)));
        float2 pk;
        *reinterpret_cast<__half2*>(&pk.x) = o0;
        *reinterpret_cast<__half2*>(&pk.y) = o1;
        ((float2*)g_agg16)[(size_t)w * 24 + lane] = pk;
    }
}

// ---------------- fused tail: pooling + MLP1 + MLP2 (fp16 agg) --------------
__global__ void tail_k(const float* __restrict__ Wo1, const float* __restrict__ bo1,
                       const float* __restrict__ Wo2, const float* __restrict__ bo2,
                       float* __restrict__ out) {
    int g = blockIdx.x;
    int beg = g_goff[g], end = g_goff[g + 1];
    int t = threadIdx.x;                 // 288 threads = 3 x 96
    int f = t % DM, rr = t / DM;
    __shared__ float smx[288], ssm[288];
    __shared__ float pooled[2 * DM];
    __shared__ float hidden[DM];

    float mx = -INFINITY, sm = 0.0f;
    for (int n = beg + rr; n < end; n += 3) {
        float v = __half2float(g_agg16[(size_t)n * DM + f]);
        mx = fmaxf(mx, v);
        sm += v;
    }
    smx[t] = mx;
    ssm[t] = sm;
    __syncthreads();
    if (rr == 0) {
        mx = fmaxf(fmaxf(smx[f], smx[f + DM]), smx[f + 2 * DM]);
        sm = ssm[f] + ssm[f + DM] + ssm[f + 2 * DM];
        pooled[f] = mx;
        pooled[DM + f] = sm / fmaxf((float)(end - beg), 1.0f);
    }
    __syncthreads();
    if (t < DM) {
        float acc = bo1[t];
#pragma unroll 8
        for (int k = 0; k < 2 * DM; k++) acc = fmaf(pooled[k], Wo1[k * DM + t], acc);
        hidden[t] = lrelu(acc);
    }
    __syncthreads();
    if (t < 32) {
        float a = 0.0f;
#pragma unroll
        for (int k = t; k < DM; k += 32) a = fmaf(hidden[k], Wo2[k], a);
#pragma unroll
        for (int o = 16; o; o >>= 1) a += __shfl_down_sync(0xffffffff, a, o);
        if (t == 0) out[g] = a + bo2[0];
    }
}

// ---------------- host orchestration ---------------------------------------
extern "C" void kernel_launch(void* const* d_in, const int* in_sizes, int n_in,
                              void* d_out, int out_size) {
    const float* x      = (const float*)d_in[0];
    const void*  ei     = d_in[1];
    const void*  batch  = d_in[2];
    const float* W_init = (const float*)d_in[3];
    const float* b_init = (const float*)d_in[4];
    const float* Wl[4]  = {(const float*)d_in[5], (const float*)d_in[7],
                           (const float*)d_in[9], (const float*)d_in[11]};
    const float* bl[4]  = {(const float*)d_in[6], (const float*)d_in[8],
                           (const float*)d_in[10], (const float*)d_in[12]};
    const float* Wo1    = (const float*)d_in[13];
    const float* bo1    = (const float*)d_in[14];
    const float* Wo2    = (const float*)d_in[15];
    const float* bo2    = (const float*)d_in[16];
    float* out = (float*)d_out;

    __half* p_aggx16 = nullptr;
    __half* p_agg16 = nullptr;
    cudaGetSymbolAddress((void**)&p_aggx16, g_aggx16);
    cudaGetSymbolAddress((void**)&p_agg16, g_agg16);

    const int T = 256;
    const int gridE   = (N_EDGES + T - 1) / T;
    const int gridG   = (N_NODES * 32 + T - 1) / T;   // warp per node
    const int gridG16 = (N_NODES * 8 + T - 1) / T;    // 8 lanes per node
    const int gridMM  = N_PAD / 128;                  // 391

    init_k<<<NBLK_N, T>>>((const int*)ei);
    count_k<<<gridE, T>>>(ei, batch);
    scanpart_dis_k<<<NBLK_N, T>>>(x);
    scantop_goff_k<<<1, T>>>();
    scan_down_k<<<NBLK_N, T>>>();
    bucket_k<<<gridE, T>>>(ei);

    // layer 1: aggregate in 16-dim input space, then wmma GEMM + lrelu(+b)
    gather16_k<<<gridG16, T>>>();
    gemm_wmma_k<FIN0, 1><<<gridMM, 256>>>(p_aggx16, W_init, b_init);

    // layers 2..5 (K=96)
    for (int l = 0; l < 4; l++) {
        gemm_wmma_k<DM, 0><<<gridMM, 256>>>(p_agg16, Wl[l], nullptr);
        gather_k<<<gridG, T>>>(bl[l]);
    }

    // fused pooling + MLP head
    tail_k<<<NG, 288>>>(Wo1, bo1, Wo2, bo2, out);
}